// round 12
// baseline (speedup 1.0000x reference)
#include <cuda_runtime.h>
#include <cstdint>

#define B_ 128
#define I_ 64
#define S_ 2048
#define H_ 128
#define O_ 64
#define G4H 512
#define GB 16
#define GH 8
#define BPG 8
#define HPG 16
#define THREADS 512

typedef unsigned long long ull;

__device__ float g_xT[(size_t)GB * S_ * (BPG * I_)];  // [bi][t][b*64+i]
__device__ float g_hs[(size_t)B_ * S_ * H_];          // [b][t][h]
__device__ float g_h[B_ * H_];
__device__ float g_xin[B_ * H_];
__device__ float g_hin[B_ * H_];

#define OFF_X1 0        // 8 sections x (24k x 8b + 4 pad) = 1568 f
#define OFF_X2 1568     // 8 sections x (32k x 8b + 4 pad) = 2080 f
#define MBAR_F 16704    // 2 mbarriers (8B each), above projection usage
#define SMEM_FLOATS 16708
#define SMEM_BYTES (SMEM_FLOATS * 4)

#define FMA2(d,a,b,c)  asm("fma.rn.f32x2 %0, %1, %2, %3;" : "=l"(d) : "l"(a), "l"(b), "l"(c))
#define PACK2(d,lo,hi) asm("mov.b64 %0, {%1, %2};" : "=l"(d) : "f"(lo), "f"(hi))
#define UNPACK2(lo,hi,s) asm("mov.b64 {%0, %1}, %2;" : "=f"(lo), "=f"(hi) : "l"(s))

__device__ __forceinline__ float tanhapx(float x) {
    float y; asm("tanh.approx.f32 %0, %1;" : "=f"(y) : "f"(x)); return y;
}
__device__ __forceinline__ uint32_t smem_u32(const void* p) {
    uint32_t a;
    asm("{ .reg .u64 t; cvta.to.shared.u64 t, %1; cvt.u32.u64 %0, t; }" : "=r"(a) : "l"(p));
    return a;
}
__device__ __forceinline__ void cluster_sync() {
    asm volatile("barrier.cluster.arrive.aligned;\n\t"
                 "barrier.cluster.wait.aligned;" ::: "memory");
}
__device__ __forceinline__ void arrive_all(uint32_t mb) {
#pragma unroll
    for (int r = 0; r < GH; r++) {
        uint32_t ra;
        asm("mapa.shared::cluster.u32 %0, %1, %2;" : "=r"(ra) : "r"(mb), "r"(r));
        asm volatile("mbarrier.arrive.shared::cluster.b64 _, [%0];" :: "r"(ra) : "memory");
    }
}
__device__ __forceinline__ void waitp(uint32_t mb, uint32_t par) {
    uint32_t done;
    do {
        asm volatile("{\n\t.reg .pred p;\n\t"
            "mbarrier.try_wait.parity.acquire.cluster.shared::cta.b64 p, [%1], %2, 0x989680;\n\t"
            "selp.b32 %0, 1, 0, p;\n\t}"
            : "=r"(done) : "r"(mb), "r"(par) : "memory");
    } while (!done);
}

__global__ void __cluster_dims__(GH, 1, 1) __launch_bounds__(THREADS, 1)
nlstm_fused(const float* __restrict__ x,
            const float* __restrict__ Wx_out, const float* __restrict__ Wh_out,
            const float* __restrict__ b_out,
            const float* __restrict__ Wx_in,  const float* __restrict__ Wh_in,
            const float* __restrict__ b_in,
            const float* __restrict__ W_lin,  const float* __restrict__ b_lin,
            float* __restrict__ out)
{
    extern __shared__ float sm[];
    const int tid = threadIdx.x;
    const int hj = blockIdx.x, bi = blockIdx.y;     // 0..7 h/t-slice, 0..15 batch group
    const int bg0 = bi * BPG, hg0 = hj * HPG;
    const uint32_t sbase = smem_u32(sm);
    const uint32_t mbA = sbase + MBAR_F * 4, mbB = mbA + 8;

    // ---------- phase 0: cluster-local transpose ----------
    {
        const float* xbg = x + (size_t)bg0 * I_ * S_;
        float* xTbg = g_xT + (size_t)bi * S_ * (BPG * I_);
        const int t0 = hj * 256;
        float* tile = sm;                     // [64][257]
        for (int rt = 0; rt < 8; rt++) {
            int r0 = rt * 64;
            for (int idx = tid; idx < 64 * 256; idx += THREADS) {
                int r = idx >> 8, tt = idx & 255;
                tile[r * 257 + tt] = xbg[(size_t)(r0 + r) * S_ + t0 + tt];
            }
            __syncthreads();
            for (int idx = tid; idx < 64 * 256; idx += THREADS) {
                int tt = idx >> 6, r = idx & 63;
                xTbg[(size_t)(t0 + tt) * (BPG * I_) + r0 + r] = tile[r * 257 + tt];
            }
            __syncthreads();
        }
    }

    // ---------- phase 1: roles, register weights, init ----------
    const int w = tid >> 5, lane = tid & 31, g = lane >> 3, kq = lane & 7;
    const int hh = hg0 + w, gcol = g * H_ + hh;

    float w1r[24], w2r[32];
#pragma unroll
    for (int j = 0; j < 24; j++) {
        int k = kq * 24 + j;
        w1r[j] = (k < I_) ? Wx_out[k * G4H + gcol] : Wh_out[(k - I_) * G4H + gcol];
    }
#pragma unroll
    for (int j = 0; j < 32; j++) {
        int k = kq * 32 + j;
        w2r[j] = (k < H_) ? Wx_in[k * G4H + gcol] : Wh_in[(k - H_) * G4H + gcol];
    }
    const float b1 = b_out[gcol], b2 = b_in[gcol];
    const float actA = (g == 3) ? 1.f : 0.5f;
    const float actS = (g == 3) ? 1.f : 0.5f;
    const float actC = (g == 3) ? 0.f : 0.5f;

    float* const pxin = &g_xin[(bg0 + kq) * H_ + hh];
    float* const phin = &g_hin[(bg0 + kq) * H_ + hh];
    float* const ph   = &g_h  [(bg0 + kq) * H_ + hh];
    float*       phs  = &g_hs [(size_t)(bg0 + kq) * S_ * H_ + hh];

    const int bx = tid >> 6, ix = tid & 63, kqx = ix / 24, jx = ix - kqx * 24;
    float st_c = 0.f, st_cn = 0.f, st_o = 0.f;

    if (tid == 0) {
        asm volatile("mbarrier.init.shared.b64 [%0], %1;" :: "r"(mbA), "r"(GH) : "memory");
        asm volatile("mbarrier.init.shared.b64 [%0], %1;" :: "r"(mbB), "r"(GH) : "memory");
    }
    __syncthreads();
    cluster_sync();    // g_xT + mbarriers visible cluster-wide

    const float* xTbg = g_xT + (size_t)bi * S_ * (BPG * I_);

    // ---------- phase 2: recurrence ----------
    for (int t = 0; t < S_; t++) {
        float xv = __ldcg(&xTbg[(size_t)t * (BPG * I_) + tid]);   // overlap with wait
        if (t > 0) waitp(mbB, (t - 1) & 1);

        // stage sX1 = [x(t) | h(t-1)]
        sm[OFF_X1 + kqx * 196 + jx * 8 + bx] = xv;
#pragma unroll
        for (int rep = 0; rep < 2; rep++) {
            int idx = tid + rep * THREADS, b = idx >> 7, h2 = idx & 127;
            float hv = (t == 0) ? 0.f : __ldcg(&g_h[(bg0 + b) * H_ + h2]);
            int k = I_ + h2, kqs = k / 24, js = k - kqs * 24;
            sm[OFF_X1 + kqs * 196 + js * 8 + b] = hv;
        }
        __syncthreads();

        // matvec 1 (register weights, 24 k, 8 batches via f32x2)
        ull a0 = 0, a1 = 0, a2 = 0, a3 = 0;
        {
            const float* xp = sm + OFF_X1 + kq * 196;
#pragma unroll
            for (int j = 0; j < 24; j++) {
                ull wp; PACK2(wp, w1r[j], w1r[j]);
                ulonglong2 xa = *(const ulonglong2*)(xp + j * 8);
                ulonglong2 xb = *(const ulonglong2*)(xp + j * 8 + 4);
                FMA2(a0, wp, xa.x, a0); FMA2(a1, wp, xa.y, a1);
                FMA2(a2, wp, xb.x, a2); FMA2(a3, wp, xb.y, a3);
            }
        }
        // warp k-reduce + act1
        {
            float s0, s1, s2, s3, s4, s5, s6, s7;
            UNPACK2(s0, s1, a0); UNPACK2(s2, s3, a1);
            UNPACK2(s4, s5, a2); UNPACK2(s6, s7, a3);
#pragma unroll
            for (int m = 1; m < 8; m <<= 1) {
                s0 += __shfl_xor_sync(~0u, s0, m); s1 += __shfl_xor_sync(~0u, s1, m);
                s2 += __shfl_xor_sync(~0u, s2, m); s3 += __shfl_xor_sync(~0u, s3, m);
                s4 += __shfl_xor_sync(~0u, s4, m); s5 += __shfl_xor_sync(~0u, s5, m);
                s6 += __shfl_xor_sync(~0u, s6, m); s7 += __shfl_xor_sync(~0u, s7, m);
            }
            float u0 = (kq & 1) ? s1 : s0, u1 = (kq & 1) ? s3 : s2;
            float u2 = (kq & 1) ? s5 : s4, u3 = (kq & 1) ? s7 : s6;
            float v0 = (kq & 2) ? u1 : u0, v1 = (kq & 2) ? u3 : u2;
            float v  = (kq & 4) ? v1 : v0;
            float y = fmaf(actA, tanhapx(actS * (v + b1)), actC);
            float p  = __shfl_xor_sync(~0u, y, 8);
            float qv = __shfl_xor_sync(~0u, y, 16);
            float r  = __shfl_xor_sync(~0u, p, 16);
            float gi = (g == 0) ? y : (g == 1) ? p : (g == 2) ? qv : r;
            float gf = (g == 1) ? y : (g == 0) ? p : (g == 3) ? qv : r;
            float go = (g == 2) ? y : (g == 3) ? p : (g == 0) ? qv : r;
            float gg = (g == 3) ? y : (g == 2) ? p : (g == 1) ? qv : r;
            st_o = go;
            if (g == 0)      __stcg(pxin, gi * gg);
            else if (g == 1) __stcg(phin, gf * st_c);
        }
        __syncthreads();
        if (tid == 0) { asm volatile("fence.acq_rel.cluster;" ::: "memory"); arrive_all(mbA); }
        waitp(mbA, t & 1);

        // stage sX2 = [x_in | h_in]
#pragma unroll
        for (int rep = 0; rep < 4; rep++) {
            int idx = tid + rep * THREADS, b = idx >> 8, k = idx & 255;
            float v = (k < H_) ? __ldcg(&g_xin[(bg0 + b) * H_ + k])
                               : __ldcg(&g_hin[(bg0 + b) * H_ + (k - H_)]);
            sm[OFF_X2 + (k >> 5) * 260 + (k & 31) * 8 + b] = v;
        }
        __syncthreads();

        // matvec 2 (register weights, 32 k)
        a0 = 0; a1 = 0; a2 = 0; a3 = 0;
        {
            const float* xp = sm + OFF_X2 + kq * 260;
#pragma unroll
            for (int j = 0; j < 32; j++) {
                ull wp; PACK2(wp, w2r[j], w2r[j]);
                ulonglong2 xa = *(const ulonglong2*)(xp + j * 8);
                ulonglong2 xb = *(const ulonglong2*)(xp + j * 8 + 4);
                FMA2(a0, wp, xa.x, a0); FMA2(a1, wp, xa.y, a1);
                FMA2(a2, wp, xb.x, a2); FMA2(a3, wp, xb.y, a3);
            }
        }
        // warp k-reduce + act2
        {
            float s0, s1, s2, s3, s4, s5, s6, s7;
            UNPACK2(s0, s1, a0); UNPACK2(s2, s3, a1);
            UNPACK2(s4, s5, a2); UNPACK2(s6, s7, a3);
#pragma unroll
            for (int m = 1; m < 8; m <<= 1) {
                s0 += __shfl_xor_sync(~0u, s0, m); s1 += __shfl_xor_sync(~0u, s1, m);
                s2 += __shfl_xor_sync(~0u, s2, m); s3 += __shfl_xor_sync(~0u, s3, m);
                s4 += __shfl_xor_sync(~0u, s4, m); s5 += __shfl_xor_sync(~0u, s5, m);
                s6 += __shfl_xor_sync(~0u, s6, m); s7 += __shfl_xor_sync(~0u, s7, m);
            }
            float u0 = (kq & 1) ? s1 : s0, u1 = (kq & 1) ? s3 : s2;
            float u2 = (kq & 1) ? s5 : s4, u3 = (kq & 1) ? s7 : s6;
            float v0 = (kq & 2) ? u1 : u0, v1 = (kq & 2) ? u3 : u2;
            float v  = (kq & 4) ? v1 : v0;
            float y = fmaf(actA, tanhapx(actS * (v + b2)), actC);
            float p  = __shfl_xor_sync(~0u, y, 8);
            float qv = __shfl_xor_sync(~0u, y, 16);
            float r  = __shfl_xor_sync(~0u, p, 16);
            float gi = (g == 0) ? y : (g == 1) ? p : (g == 2) ? qv : r;
            float gf = (g == 1) ? y : (g == 0) ? p : (g == 3) ? qv : r;
            float go = (g == 2) ? y : (g == 3) ? p : (g == 0) ? qv : r;
            float gg = (g == 3) ? y : (g == 2) ? p : (g == 1) ? qv : r;
            st_cn = fmaf(gf, st_cn, gi * gg);
            float cv = go * tanhapx(st_cn);
            st_c = cv;
            float hv = st_o * tanhapx(cv);
            if (g == 2)      __stcg(ph, hv);
            else if (g == 3) __stcg(phs, hv);
        }
        phs += H_;
        __syncthreads();
        if (tid == 0) { asm volatile("fence.acq_rel.cluster;" ::: "memory"); arrive_all(mbB); }
    }
    cluster_sync();   // all g_hs slices complete + visible

    // ---------- phase 3: cluster-local projection ----------
    {
        float* sWt   = sm;                   // [128 k][64 o] = 8192 f
        float* sTile = sm + 8192;            // [64 r][132]   = 8448 f
        float* sBL   = sm + 8192 + 8448;     // 64 f
        for (int idx = tid; idx < H_ * O_; idx += THREADS) {
            int o = idx & 63, k = idx >> 6;
            sWt[k * 64 + o] = W_lin[o * H_ + k];
        }
        if (tid < O_) sBL[tid] = b_lin[tid];
        __syncthreads();

        const int t0 = hj * 256, row = tid >> 3, cg = tid & 7;
        for (int it = 0; it < 32; it++) {
            int b = it >> 2, tr0 = t0 + (it & 3) * 64;
            const float* src = g_hs + ((size_t)(bg0 + b) * S_ + tr0) * H_;
            for (int idx = tid; idx < 64 * H_; idx += THREADS) {
                int r = idx >> 7, k = idx & 127;
                sTile[r * 132 + k] = src[idx];
            }
            __syncthreads();

            float accp[8];
#pragma unroll
            for (int j = 0; j < 8; j++) accp[j] = sBL[cg * 8 + j];
            const float* hrow = sTile + row * 132;
#pragma unroll 8
            for (int k4 = 0; k4 < 32; k4++) {
                float4 hx = *(const float4*)(hrow + k4 * 4);
#pragma unroll
                for (int kk = 0; kk < 4; kk++) {
                    float hv = (kk == 0) ? hx.x : (kk == 1) ? hx.y : (kk == 2) ? hx.z : hx.w;
                    const float* wr = sWt + (k4 * 4 + kk) * 64 + cg * 8;
                    float4 w0 = *(const float4*)(wr);
                    float4 w1 = *(const float4*)(wr + 4);
                    accp[0] = fmaf(hv, w0.x, accp[0]); accp[1] = fmaf(hv, w0.y, accp[1]);
                    accp[2] = fmaf(hv, w0.z, accp[2]); accp[3] = fmaf(hv, w0.w, accp[3]);
                    accp[4] = fmaf(hv, w1.x, accp[4]); accp[5] = fmaf(hv, w1.y, accp[5]);
                    accp[6] = fmaf(hv, w1.z, accp[6]); accp[7] = fmaf(hv, w1.w, accp[7]);
                }
            }
            float* orow = out + ((size_t)(bg0 + b) * S_ + tr0 + row) * O_ + cg * 8;
            *(float4*)(orow)     = make_float4(accp[0], accp[1], accp[2], accp[3]);
            *(float4*)(orow + 4) = make_float4(accp[4], accp[5], accp[6], accp[7]);
            __syncthreads();
        }
    }
}

extern "C" void kernel_launch(void* const* d_in, const int* in_sizes, int n_in,
                              void* d_out, int out_size)
{
    const float* x      = (const float*)d_in[0];
    const float* Wx_out = (const float*)d_in[1];
    const float* Wh_out = (const float*)d_in[2];
    const float* b_out  = (const float*)d_in[3];
    const float* Wx_in  = (const float*)d_in[4];
    const float* Wh_in  = (const float*)d_in[5];
    const float* b_in   = (const float*)d_in[6];
    const float* W_lin  = (const float*)d_in[7];
    const float* b_lin  = (const float*)d_in[8];
    float* out = (float*)d_out;

    (void)cudaFuncSetAttribute(nlstm_fused,
                               cudaFuncAttributeMaxDynamicSharedMemorySize, SMEM_BYTES);
    nlstm_fused<<<dim3(GH, GB), THREADS, SMEM_BYTES>>>(
        x, Wx_out, Wh_out, b_out, Wx_in, Wh_in, b_in, W_lin, b_lin, out);
}

// round 14
// speedup vs baseline: 1.0002x; 1.0002x over previous
#include <cuda_runtime.h>
#include <cstdint>

#define B_ 128
#define I_ 64
#define S_ 2048
#define H_ 128
#define O_ 64
#define G4H 512
#define GB 16
#define GH 8
#define BPG 8
#define HPG 16
#define THREADS 512

typedef unsigned long long ull;

__device__ float g_xT[(size_t)GB * S_ * (BPG * I_)];  // [bi][t][b*64+i]
__device__ float g_hs[(size_t)B_ * S_ * H_];          // [b][t][h]
__device__ float g_h[B_ * H_];
__device__ float g_xin[B_ * H_];
__device__ float g_hin[B_ * H_];

#define OFF_X1 0        // 8 sections x (24k x 8b + 4 pad) = 1568 f
#define OFF_X2 1568     // 8 sections x (32k x 8b + 4 pad) = 2080 f
#define MBAR_F 16704    // 2 mbarriers (8B each), above projection usage
#define SMEM_FLOATS 16708
#define SMEM_BYTES (SMEM_FLOATS * 4)

#define FMA2(d,a,b,c)  asm("fma.rn.f32x2 %0, %1, %2, %3;" : "=l"(d) : "l"(a), "l"(b), "l"(c))
#define PACK2(d,lo,hi) asm("mov.b64 %0, {%1, %2};" : "=l"(d) : "f"(lo), "f"(hi))
#define UNPACK2(lo,hi,s) asm("mov.b64 {%0, %1}, %2;" : "=f"(lo), "=f"(hi) : "l"(s))

__device__ __forceinline__ float tanhapx(float x) {
    float y; asm("tanh.approx.f32 %0, %1;" : "=f"(y) : "f"(x)); return y;
}
__device__ __forceinline__ uint32_t smem_u32(const void* p) {
    uint32_t a;
    asm("{ .reg .u64 t; cvta.to.shared.u64 t, %1; cvt.u32.u64 %0, t; }" : "=r"(a) : "l"(p));
    return a;
}
__device__ __forceinline__ void cluster_sync() {
    asm volatile("barrier.cluster.arrive.aligned;\n\t"
                 "barrier.cluster.wait.aligned;" ::: "memory");
}
__device__ __forceinline__ void arrive_all(uint32_t mb) {
#pragma unroll
    for (int r = 0; r < GH; r++) {
        uint32_t ra;
        asm("mapa.shared::cluster.u32 %0, %1, %2;" : "=r"(ra) : "r"(mb), "r"(r));
        asm volatile("mbarrier.arrive.shared::cluster.b64 _, [%0];" :: "r"(ra) : "memory");
    }
}
__device__ __forceinline__ void waitp(uint32_t mb, uint32_t par) {
    uint32_t done;
    do {
        asm volatile("{\n\t.reg .pred p;\n\t"
            "mbarrier.try_wait.parity.acquire.cluster.shared::cta.b64 p, [%1], %2, 0x989680;\n\t"
            "selp.b32 %0, 1, 0, p;\n\t}"
            : "=r"(done) : "r"(mb), "r"(par) : "memory");
    } while (!done);
}

__global__ void __cluster_dims__(GH, 1, 1) __launch_bounds__(THREADS, 1)
nlstm_fused(const float* __restrict__ x,
            const float* __restrict__ Wx_out, const float* __restrict__ Wh_out,
            const float* __restrict__ b_out,
            const float* __restrict__ Wx_in,  const float* __restrict__ Wh_in,
            const float* __restrict__ b_in,
            const float* __restrict__ W_lin,  const float* __restrict__ b_lin,
            float* __restrict__ out)
{
    extern __shared__ float sm[];
    const int tid = threadIdx.x;
    const int hj = blockIdx.x, bi = blockIdx.y;     // 0..7 h/t-slice, 0..15 batch group
    const int bg0 = bi * BPG, hg0 = hj * HPG;
    const uint32_t sbase = smem_u32(sm);
    const uint32_t mbA = sbase + MBAR_F * 4, mbB = mbA + 8;

    // ---------- phase 0: cluster-local transpose ----------
    {
        const float* xbg = x + (size_t)bg0 * I_ * S_;
        float* xTbg = g_xT + (size_t)bi * S_ * (BPG * I_);
        const int t0 = hj * 256;
        float* tile = sm;                     // [64][257]
        for (int rt = 0; rt < 8; rt++) {
            int r0 = rt * 64;
            for (int idx = tid; idx < 64 * 256; idx += THREADS) {
                int r = idx >> 8, tt = idx & 255;
                tile[r * 257 + tt] = xbg[(size_t)(r0 + r) * S_ + t0 + tt];
            }
            __syncthreads();
            for (int idx = tid; idx < 64 * 256; idx += THREADS) {
                int tt = idx >> 6, r = idx & 63;
                xTbg[(size_t)(t0 + tt) * (BPG * I_) + r0 + r] = tile[r * 257 + tt];
            }
            __syncthreads();
        }
    }

    // ---------- phase 1: roles, register weights, init ----------
    const int w = tid >> 5, lane = tid & 31, g = lane >> 3, kq = lane & 7;
    const int hh = hg0 + w, gcol = g * H_ + hh;

    float w1r[24], w2r[32];
#pragma unroll
    for (int j = 0; j < 24; j++) {
        int k = kq * 24 + j;
        w1r[j] = (k < I_) ? Wx_out[k * G4H + gcol] : Wh_out[(k - I_) * G4H + gcol];
    }
#pragma unroll
    for (int j = 0; j < 32; j++) {
        int k = kq * 32 + j;
        w2r[j] = (k < H_) ? Wx_in[k * G4H + gcol] : Wh_in[(k - H_) * G4H + gcol];
    }
    const float b1 = b_out[gcol], b2 = b_in[gcol];
    const float actA = (g == 3) ? 1.f : 0.5f;
    const float actS = (g == 3) ? 1.f : 0.5f;
    const float actC = (g == 3) ? 0.f : 0.5f;

    float* const pxin = &g_xin[(bg0 + kq) * H_ + hh];
    float* const phin = &g_hin[(bg0 + kq) * H_ + hh];
    float* const ph   = &g_h  [(bg0 + kq) * H_ + hh];
    float*       phs  = &g_hs [(size_t)(bg0 + kq) * S_ * H_ + hh];

    const int bx = tid >> 6, ix = tid & 63, kqx = ix / 24, jx = ix - kqx * 24;
    float st_c = 0.f, st_cn = 0.f, st_o = 0.f;

    if (tid == 0) {
        asm volatile("mbarrier.init.shared.b64 [%0], %1;" :: "r"(mbA), "r"(GH) : "memory");
        asm volatile("mbarrier.init.shared.b64 [%0], %1;" :: "r"(mbB), "r"(GH) : "memory");
    }
    __syncthreads();
    cluster_sync();    // g_xT + mbarriers visible cluster-wide

    const float* xTbg = g_xT + (size_t)bi * S_ * (BPG * I_);

    // ---------- phase 2: recurrence ----------
    for (int t = 0; t < S_; t++) {
        float xv = __ldcg(&xTbg[(size_t)t * (BPG * I_) + tid]);   // overlap with wait
        if (t > 0) waitp(mbB, (t - 1) & 1);

        // stage sX1 = [x(t) | h(t-1)]
        sm[OFF_X1 + kqx * 196 + jx * 8 + bx] = xv;
#pragma unroll
        for (int rep = 0; rep < 2; rep++) {
            int idx = tid + rep * THREADS, b = idx >> 7, h2 = idx & 127;
            float hv = (t == 0) ? 0.f : __ldcg(&g_h[(bg0 + b) * H_ + h2]);
            int k = I_ + h2, kqs = k / 24, js = k - kqs * 24;
            sm[OFF_X1 + kqs * 196 + js * 8 + b] = hv;
        }
        __syncthreads();

        // matvec 1 (register weights, 24 k, 8 batches via f32x2)
        ull a0 = 0, a1 = 0, a2 = 0, a3 = 0;
        {
            const float* xp = sm + OFF_X1 + kq * 196;
#pragma unroll
            for (int j = 0; j < 24; j++) {
                ull wp; PACK2(wp, w1r[j], w1r[j]);
                ulonglong2 xa = *(const ulonglong2*)(xp + j * 8);
                ulonglong2 xb = *(const ulonglong2*)(xp + j * 8 + 4);
                FMA2(a0, wp, xa.x, a0); FMA2(a1, wp, xa.y, a1);
                FMA2(a2, wp, xb.x, a2); FMA2(a3, wp, xb.y, a3);
            }
        }
        // warp k-reduce + act1
        {
            float s0, s1, s2, s3, s4, s5, s6, s7;
            UNPACK2(s0, s1, a0); UNPACK2(s2, s3, a1);
            UNPACK2(s4, s5, a2); UNPACK2(s6, s7, a3);
#pragma unroll
            for (int m = 1; m < 8; m <<= 1) {
                s0 += __shfl_xor_sync(~0u, s0, m); s1 += __shfl_xor_sync(~0u, s1, m);
                s2 += __shfl_xor_sync(~0u, s2, m); s3 += __shfl_xor_sync(~0u, s3, m);
                s4 += __shfl_xor_sync(~0u, s4, m); s5 += __shfl_xor_sync(~0u, s5, m);
                s6 += __shfl_xor_sync(~0u, s6, m); s7 += __shfl_xor_sync(~0u, s7, m);
            }
            float u0 = (kq & 1) ? s1 : s0, u1 = (kq & 1) ? s3 : s2;
            float u2 = (kq & 1) ? s5 : s4, u3 = (kq & 1) ? s7 : s6;
            float v0 = (kq & 2) ? u1 : u0, v1 = (kq & 2) ? u3 : u2;
            float v  = (kq & 4) ? v1 : v0;
            float y = fmaf(actA, tanhapx(actS * (v + b1)), actC);
            float p  = __shfl_xor_sync(~0u, y, 8);
            float qv = __shfl_xor_sync(~0u, y, 16);
            float r  = __shfl_xor_sync(~0u, p, 16);
            float gi = (g == 0) ? y : (g == 1) ? p : (g == 2) ? qv : r;
            float gf = (g == 1) ? y : (g == 0) ? p : (g == 3) ? qv : r;
            float go = (g == 2) ? y : (g == 3) ? p : (g == 0) ? qv : r;
            float gg = (g == 3) ? y : (g == 2) ? p : (g == 1) ? qv : r;
            st_o = go;
            if (g == 0)      __stcg(pxin, gi * gg);
            else if (g == 1) __stcg(phin, gf * st_c);
        }
        __syncthreads();
        if (tid == 0) { asm volatile("fence.acq_rel.cluster;" ::: "memory"); arrive_all(mbA); }
        waitp(mbA, t & 1);

        // stage sX2 = [x_in | h_in]
#pragma unroll
        for (int rep = 0; rep < 4; rep++) {
            int idx = tid + rep * THREADS, b = idx >> 8, k = idx & 255;
            float v = (k < H_) ? __ldcg(&g_xin[(bg0 + b) * H_ + k])
                               : __ldcg(&g_hin[(bg0 + b) * H_ + (k - H_)]);
            sm[OFF_X2 + (k >> 5) * 260 + (k & 31) * 8 + b] = v;
        }
        __syncthreads();

        // matvec 2 (register weights, 32 k)
        a0 = 0; a1 = 0; a2 = 0; a3 = 0;
        {
            const float* xp = sm + OFF_X2 + kq * 260;
#pragma unroll
            for (int j = 0; j < 32; j++) {
                ull wp; PACK2(wp, w2r[j], w2r[j]);
                ulonglong2 xa = *(const ulonglong2*)(xp + j * 8);
                ulonglong2 xb = *(const ulonglong2*)(xp + j * 8 + 4);
                FMA2(a0, wp, xa.x, a0); FMA2(a1, wp, xa.y, a1);
                FMA2(a2, wp, xb.x, a2); FMA2(a3, wp, xb.y, a3);
            }
        }
        // warp k-reduce + act2
        {
            float s0, s1, s2, s3, s4, s5, s6, s7;
            UNPACK2(s0, s1, a0); UNPACK2(s2, s3, a1);
            UNPACK2(s4, s5, a2); UNPACK2(s6, s7, a3);
#pragma unroll
            for (int m = 1; m < 8; m <<= 1) {
                s0 += __shfl_xor_sync(~0u, s0, m); s1 += __shfl_xor_sync(~0u, s1, m);
                s2 += __shfl_xor_sync(~0u, s2, m); s3 += __shfl_xor_sync(~0u, s3, m);
                s4 += __shfl_xor_sync(~0u, s4, m); s5 += __shfl_xor_sync(~0u, s5, m);
                s6 += __shfl_xor_sync(~0u, s6, m); s7 += __shfl_xor_sync(~0u, s7, m);
            }
            float u0 = (kq & 1) ? s1 : s0, u1 = (kq & 1) ? s3 : s2;
            float u2 = (kq & 1) ? s5 : s4, u3 = (kq & 1) ? s7 : s6;
            float v0 = (kq & 2) ? u1 : u0, v1 = (kq & 2) ? u3 : u2;
            float v  = (kq & 4) ? v1 : v0;
            float y = fmaf(actA, tanhapx(actS * (v + b2)), actC);
            float p  = __shfl_xor_sync(~0u, y, 8);
            float qv = __shfl_xor_sync(~0u, y, 16);
            float r  = __shfl_xor_sync(~0u, p, 16);
            float gi = (g == 0) ? y : (g == 1) ? p : (g == 2) ? qv : r;
            float gf = (g == 1) ? y : (g == 0) ? p : (g == 3) ? qv : r;
            float go = (g == 2) ? y : (g == 3) ? p : (g == 0) ? qv : r;
            float gg = (g == 3) ? y : (g == 2) ? p : (g == 1) ? qv : r;
            st_cn = fmaf(gf, st_cn, gi * gg);
            float cv = go * tanhapx(st_cn);
            st_c = cv;
            float hv = st_o * tanhapx(cv);
            if (g == 2)      __stcg(ph, hv);
            else if (g == 3) __stcg(phs, hv);
        }
        phs += H_;
        __syncthreads();
        if (tid == 0) { asm volatile("fence.acq_rel.cluster;" ::: "memory"); arrive_all(mbB); }
    }
    cluster_sync();   // all g_hs slices complete + visible

    // ---------- phase 3: cluster-local projection ----------
    {
        float* sWt   = sm;                   // [128 k][64 o] = 8192 f
        float* sTile = sm + 8192;            // [64 r][132]   = 8448 f
        float* sBL   = sm + 8192 + 8448;     // 64 f
        for (int idx = tid; idx < H_ * O_; idx += THREADS) {
            int o = idx & 63, k = idx >> 6;
            sWt[k * 64 + o] = W_lin[o * H_ + k];
        }
        if (tid < O_) sBL[tid] = b_lin[tid];
        __syncthreads();

        const int t0 = hj * 256, row = tid >> 3, cg = tid & 7;
        for (int it = 0; it < 32; it++) {
            int b = it >> 2, tr0 = t0 + (it & 3) * 64;
            const float* src = g_hs + ((size_t)(bg0 + b) * S_ + tr0) * H_;
            for (int idx = tid; idx < 64 * H_; idx += THREADS) {
                int r = idx >> 7, k = idx & 127;
                sTile[r * 132 + k] = src[idx];
            }
            __syncthreads();

            float accp[8];
#pragma unroll
            for (int j = 0; j < 8; j++) accp[j] = sBL[cg * 8 + j];
            const float* hrow = sTile + row * 132;
#pragma unroll 8
            for (int k4 = 0; k4 < 32; k4++) {
                float4 hx = *(const float4*)(hrow + k4 * 4);
#pragma unroll
                for (int kk = 0; kk < 4; kk++) {
                    float hv = (kk == 0) ? hx.x : (kk == 1) ? hx.y : (kk == 2) ? hx.z : hx.w;
                    const float* wr = sWt + (k4 * 4 + kk) * 64 + cg * 8;
                    float4 w0 = *(const float4*)(wr);
                    float4 w1 = *(const float4*)(wr + 4);
                    accp[0] = fmaf(hv, w0.x, accp[0]); accp[1] = fmaf(hv, w0.y, accp[1]);
                    accp[2] = fmaf(hv, w0.z, accp[2]); accp[3] = fmaf(hv, w0.w, accp[3]);
                    accp[4] = fmaf(hv, w1.x, accp[4]); accp[5] = fmaf(hv, w1.y, accp[5]);
                    accp[6] = fmaf(hv, w1.z, accp[6]); accp[7] = fmaf(hv, w1.w, accp[7]);
                }
            }
            float* orow = out + ((size_t)(bg0 + b) * S_ + tr0 + row) * O_ + cg * 8;
            *(float4*)(orow)     = make_float4(accp[0], accp[1], accp[2], accp[3]);
            *(float4*)(orow + 4) = make_float4(accp[4], accp[5], accp[6], accp[7]);
            __syncthreads();
        }
    }
}

extern "C" void kernel_launch(void* const* d_in, const int* in_sizes, int n_in,
                              void* d_out, int out_size)
{
    const float* x      = (const float*)d_in[0];
    const float* Wx_out = (const float*)d_in[1];
    const float* Wh_out = (const float*)d_in[2];
    const float* b_out  = (const float*)d_in[3];
    const float* Wx_in  = (const float*)d_in[4];
    const float* Wh_in  = (const float*)d_in[5];
    const float* b_in   = (const float*)d_in[6];
    const float* W_lin  = (const float*)d_in[7];
    const float* b_lin  = (const float*)d_in[8];
    float* out = (float*)d_out;

    (void)cudaFuncSetAttribute(nlstm_fused,
                               cudaFuncAttributeMaxDynamicSharedMemorySize, SMEM_BYTES);
    nlstm_fused<<<dim3(GH, GB), THREADS, SMEM_BYTES>>>(
        x, Wx_out, Wh_out, b_out, Wx_in, Wh_in, b_in, W_lin, b_lin, out);
}

// round 15
// speedup vs baseline: 2.7116x; 2.7111x over previous
#include <cuda_runtime.h>
#include <cstdint>

#define B_ 128
#define I_ 64
#define S_ 2048
#define H_ 128
#define O_ 64
#define G4H 512
#define NC 32          // clusters
#define GH 8           // CTAs per cluster (h-slices, 16 h each)
#define BPC 4          // batches per cluster
#define THREADS 256

typedef unsigned long long ull;

// ---------------- device scratch (static) ----------------
__device__ float g_gx[(size_t)NC * S_ * GH * BPC * 64];  // [bi][t][hj][b][cl], 512MB
__device__ float g_hs[(size_t)B_ * S_ * H_];             // [b][t][h]

// ---------------- smem layout (float offsets) ----------------
// W1 (Wh_out slice): float4 idx = kq*513 + j*64 + cl   (4 sections, j<8)
// W2 (W_in slice)  : float4 idx = kq*1025 + j*64 + cl  (4 sections, j<16)
// sX1: f(k,b) = k*4 + (k>>5)*4 + b   (k<128)  -> contiguous float4 per k, pad/32k
// sX2: same, k<256
#define OFF_W1 0
#define OFF_W2 8208
#define OFF_X1 24608
#define OFF_X2 25136
#define SMEM_FLOATS 26192
#define SMEM_BYTES (SMEM_FLOATS * 4)   // 104768 B -> 2 CTAs/SM

#define FMA2(d,a,b,c)  asm("fma.rn.f32x2 %0, %1, %2, %3;" : "=l"(d) : "l"(a), "l"(b), "l"(c))
#define PACK2(d,lo,hi) asm("mov.b64 %0, {%1, %2};" : "=l"(d) : "f"(lo), "f"(hi))
#define UNPACK2(lo,hi,s) asm("mov.b64 {%0, %1}, %2;" : "=f"(lo), "=f"(hi) : "l"(s))

__device__ __forceinline__ float tanhapx(float x) {
    float y; asm("tanh.approx.f32 %0, %1;" : "=f"(y) : "f"(x)); return y;
}
__device__ __forceinline__ uint32_t smem_u32(const void* p) {
    uint32_t a;
    asm("{ .reg .u64 t; cvta.to.shared.u64 t, %1; cvt.u32.u64 %0, t; }" : "=r"(a) : "l"(p));
    return a;
}
__device__ __forceinline__ uint32_t mapa_rank(uint32_t laddr, uint32_t rank) {
    uint32_t ra;
    asm("mapa.shared::cluster.u32 %0, %1, %2;" : "=r"(ra) : "r"(laddr), "r"(rank));
    return ra;
}
__device__ __forceinline__ void stc(uint32_t a, float v) {
    asm volatile("st.shared::cluster.f32 [%0], %1;" :: "r"(a), "f"(v) : "memory");
}
#define CLUSTER_ARRIVE() asm volatile("barrier.cluster.arrive.aligned;" ::: "memory")
#define CLUSTER_WAIT()   asm volatile("barrier.cluster.wait.aligned;"   ::: "memory")
__device__ __forceinline__ void cluster_sync() { CLUSTER_ARRIVE(); CLUSTER_WAIT(); }

// ================= pre-pass: gx = x_t @ Wx_out + b_out =================
// grid (8 tchunks, GH, NC), 256 threads. Writes g_gx[bi][t][hj][b][cl].
__global__ __launch_bounds__(256) void prepass(const float* __restrict__ x,
                                               const float* __restrict__ Wx_out,
                                               const float* __restrict__ b_out)
{
    __shared__ float sW[64 * 64];       // [i][cl]
    __shared__ float sx[4 * 64 * 16];   // [b][i][16t]
    const int tid = threadIdx.x;
    const int tc = blockIdx.x, hj = blockIdx.y, bi = blockIdx.z;
    const int cl = tid & 63, b = tid >> 6;
    const int gcl = (cl & 3) * H_ + hj * 16 + (cl >> 2);

    for (int idx = tid; idx < 64 * 64; idx += 256) {
        int i = idx >> 6, c2 = idx & 63;
        int gc2 = (c2 & 3) * H_ + hj * 16 + (c2 >> 2);
        sW[idx] = Wx_out[i * G4H + gc2];
    }
    const float bias = b_out[gcl];
    __syncthreads();

    for (int tile = 0; tile < 16; tile++) {
        int t0 = tc * 256 + tile * 16;
        for (int n = 0; n < 16; n++) {
            int flat = n * 256 + tid;
            int ttl = flat & 15, i = (flat >> 4) & 63, bb = flat >> 10;
            sx[(bb * 64 + i) * 16 + ttl] =
                x[((size_t)(bi * 4 + bb) * 64 + i) * S_ + t0 + ttl];
        }
        __syncthreads();

        ull acc[8];
#pragma unroll
        for (int tp = 0; tp < 8; tp++) PACK2(acc[tp], bias, bias);
#pragma unroll 8
        for (int i = 0; i < 64; i++) {
            float wv = sW[i * 64 + cl];
            ull wp; PACK2(wp, wv, wv);
            const ull* xp = (const ull*)(sx + (b * 64 + i) * 16);
#pragma unroll
            for (int tp = 0; tp < 8; tp++) FMA2(acc[tp], wp, xp[tp], acc[tp]);
        }
        float* outp = g_gx + (((size_t)bi * S_ + t0) * GH + hj) * 256 + b * 64 + cl;
#pragma unroll
        for (int tp = 0; tp < 8; tp++) {
            float lo, hi; UNPACK2(lo, hi, acc[tp]);
            outp[(size_t)(2 * tp) * 2048]     = lo;
            outp[(size_t)(2 * tp + 1) * 2048] = hi;
        }
        __syncthreads();
    }
}

// ================= main recurrent kernel =================
__global__ void __cluster_dims__(GH, 1, 1) __launch_bounds__(THREADS, 2)
nlstm_rec(const float* __restrict__ Wh_out,
          const float* __restrict__ Wx_in, const float* __restrict__ Wh_in,
          const float* __restrict__ b_in,
          const float* __restrict__ W_lin, const float* __restrict__ b_lin,
          float* __restrict__ out)
{
    extern __shared__ float sm[];
    const int tid = threadIdx.x;
    const int hj = blockIdx.x;          // 0..7
    const int bi = blockIdx.y;          // 0..31
    const int bg0 = bi * BPC;
    const int hg0 = hj * 16;
    const uint32_t sbase = smem_u32(sm);

    // ---- load weight slices into padded SMEM ----
    for (int idx = tid; idx < 128 * 64; idx += THREADS) {
        int k = idx >> 6, c2 = idx & 63;
        int gc = (c2 & 3) * H_ + hg0 + (c2 >> 2);
        int k4 = k >> 2, e = k & 3, kqq = k4 >> 3, j = k4 & 7;
        sm[OFF_W1 + (kqq * 513 + j * 64 + c2) * 4 + e] = Wh_out[k * G4H + gc];
    }
    for (int idx = tid; idx < 256 * 64; idx += THREADS) {
        int k = idx >> 6, c2 = idx & 63;
        int gc = (c2 & 3) * H_ + hg0 + (c2 >> 2);
        int k4 = k >> 2, e = k & 3, kqq = k4 >> 4, j = k4 & 15;
        sm[OFF_W2 + (kqq * 1025 + j * 64 + c2) * 4 + e] =
            (k < H_) ? Wx_in[k * G4H + gc] : Wh_in[(k - H_) * G4H + gc];
    }
    // zero staging
    for (int idx = tid; idx < 528 + 1056; idx += THREADS)
        sm[OFF_X1 + idx] = 0.0f;

    // ---- roles ----
    const int warp = tid >> 5, lane = tid & 31;
    const int cl = warp * 8 + (lane & 7);   // gate column 0..63 (= hl*4+g)
    const int kq = lane >> 3;               // k-quarter AND own batch (0..3)
    const int g  = cl & 3;                  // gate id (lane bits 0..1)
    const int hl = cl >> 2;                 // local h (0..15)
    const int gcol = g * H_ + hg0 + hl;

    const float b2 = b_in[gcol];
    const float actA = (g == 3) ? 1.f : 0.5f;
    const float actS = (g == 3) ? 1.f : 0.5f;
    const float actC = (g == 3) ? 0.f : 0.5f;

    // remote store targets (loop-invariant)
    uint32_t rA[8], rB[8];
    {
        int kA = (g == 0) ? (hg0 + hl) : (H_ + hg0 + hl);
        uint32_t aA = sbase + (uint32_t)(OFF_X2 + kA * 4 + (kA >> 5) * 4 + kq) * 4;
        int kB = hg0 + hl;
        uint32_t aB = sbase + (uint32_t)(OFF_X1 + kB * 4 + (kB >> 5) * 4 + kq) * 4;
#pragma unroll
        for (int r = 0; r < GH; r++) {
            rA[r] = mapa_rank(aA, r);
            rB[r] = mapa_rank(aB, r);
        }
    }

    // matvec pointers
    const float4*     w4a  = (const float4*)(sm + OFF_W1) + kq * 513 + cl;
    const float4*     w4b  = (const float4*)(sm + OFF_W2) + kq * 1025 + cl;
    const ulonglong2* x1q  = (const ulonglong2*)(sm + OFF_X1 + kq * 132);
    const ulonglong2* x2qa = (const ulonglong2*)(sm + OFF_X2 + kq * 264);
    const ulonglong2* x2qb = (const ulonglong2*)(sm + OFF_X2 + kq * 264 + 132);

    const float* gxp0 = g_gx + ((size_t)bi * S_ * GH + hj) * 256 + kq * 64 + cl;
    float* phs = g_hs + (size_t)(bg0 + kq) * S_ * H_ + hg0 + hl;

    float st_c = 0.f, st_cn = 0.f, st_o = 0.f;

    cluster_sync();    // weights + zeroed staging visible (intra-CTA and cluster)

    float gxv = __ldcg(gxp0);   // gx(t=0)

    // ---------------- recurrence ----------------
    for (int t = 0; t < S_; t++) {
        // ---- mv1: gates_h = h(t-1) @ Wh_out  (k = kq*32..+32) ----
        ull a01 = 0, a23 = 0;
#pragma unroll
        for (int j = 0; j < 8; j++) {
            float4 w = w4a[j * 64];
#pragma unroll
            for (int e = 0; e < 4; e++) {
                float wv = (e == 0) ? w.x : (e == 1) ? w.y : (e == 2) ? w.z : w.w;
                ull wp; PACK2(wp, wv, wv);
                ulonglong2 xv = x1q[j * 4 + e];
                FMA2(a01, wp, xv.x, a01); FMA2(a23, wp, xv.y, a23);
            }
        }
        // ---- k-reduce (xor 8,16) + act1 ----
        {
            float s0, s1, s2, s3;
            UNPACK2(s0, s1, a01); UNPACK2(s2, s3, a23);
#pragma unroll
            for (int m = 8; m <= 16; m <<= 1) {
                s0 += __shfl_xor_sync(~0u, s0, m); s1 += __shfl_xor_sync(~0u, s1, m);
                s2 += __shfl_xor_sync(~0u, s2, m); s3 += __shfl_xor_sync(~0u, s3, m);
            }
            float sv = (kq == 0) ? s0 : (kq == 1) ? s1 : (kq == 2) ? s2 : s3;
            float y = fmaf(actA, tanhapx(actS * (sv + gxv)), actC);
            float p  = __shfl_xor_sync(~0u, y, 1);
            float qv = __shfl_xor_sync(~0u, y, 2);
            float r  = __shfl_xor_sync(~0u, p, 2);
            float gi = (g == 0) ? y : (g == 1) ? p : (g == 2) ? qv : r;
            float gf = (g == 1) ? y : (g == 0) ? p : (g == 3) ? qv : r;
            float go = (g == 2) ? y : (g == 3) ? p : (g == 0) ? qv : r;
            float gg = (g == 3) ? y : (g == 2) ? p : (g == 1) ? qv : r;
            float v = (g == 0) ? (gi * gg) : (gf * st_c);   // xin | hin
            st_o = go;
            if (g < 2) {
                stc(rA[0], v); stc(rA[1], v); stc(rA[2], v); stc(rA[3], v);
                stc(rA[4], v); stc(rA[5], v); stc(rA[6], v); stc(rA[7], v);
            }
        }
        CLUSTER_ARRIVE();
        gxv = __ldcg(gxp0 + (size_t)((t + 1 < S_) ? t + 1 : t) * 2048);  // overlap barrier
        CLUSTER_WAIT();

        // ---- mv2: gi = [x_in|h_in] @ W_in  (k = kq*64..+64) ----
        a01 = 0; a23 = 0;
#pragma unroll
        for (int j = 0; j < 8; j++) {
            float4 w = w4b[j * 64];
#pragma unroll
            for (int e = 0; e < 4; e++) {
                float wv = (e == 0) ? w.x : (e == 1) ? w.y : (e == 2) ? w.z : w.w;
                ull wp; PACK2(wp, wv, wv);
                ulonglong2 xv = x2qa[j * 4 + e];
                FMA2(a01, wp, xv.x, a01); FMA2(a23, wp, xv.y, a23);
            }
        }
#pragma unroll
        for (int j = 8; j < 16; j++) {
            float4 w = w4b[j * 64];
#pragma unroll
            for (int e = 0; e < 4; e++) {
                float wv = (e == 0) ? w.x : (e == 1) ? w.y : (e == 2) ? w.z : w.w;
                ull wp; PACK2(wp, wv, wv);
                ulonglong2 xv = x2qb[(j - 8) * 4 + e];
                FMA2(a01, wp, xv.x, a01); FMA2(a23, wp, xv.y, a23);
            }
        }
        // ---- k-reduce + act2 ----
        {
            float s0, s1, s2, s3;
            UNPACK2(s0, s1, a01); UNPACK2(s2, s3, a23);
#pragma unroll
            for (int m = 8; m <= 16; m <<= 1) {
                s0 += __shfl_xor_sync(~0u, s0, m); s1 += __shfl_xor_sync(~0u, s1, m);
                s2 += __shfl_xor_sync(~0u, s2, m); s3 += __shfl_xor_sync(~0u, s3, m);
            }
            float sv = (kq == 0) ? s0 : (kq == 1) ? s1 : (kq == 2) ? s2 : s3;
            float y = fmaf(actA, tanhapx(actS * (sv + b2)), actC);
            float p  = __shfl_xor_sync(~0u, y, 1);
            float qv = __shfl_xor_sync(~0u, y, 2);
            float r  = __shfl_xor_sync(~0u, p, 2);
            float gi = (g == 0) ? y : (g == 1) ? p : (g == 2) ? qv : r;
            float gf = (g == 1) ? y : (g == 0) ? p : (g == 3) ? qv : r;
            float go = (g == 2) ? y : (g == 3) ? p : (g == 0) ? qv : r;
            float gg = (g == 3) ? y : (g == 2) ? p : (g == 1) ? qv : r;
            st_cn = fmaf(gf, st_cn, gi * gg);
            float cv = go * tanhapx(st_cn);
            st_c = cv;
            float hv = st_o * tanhapx(cv);
            if (g == 2) {
                stc(rB[0], hv); stc(rB[1], hv); stc(rB[2], hv); stc(rB[3], hv);
                stc(rB[4], hv); stc(rB[5], hv); stc(rB[6], hv); stc(rB[7], hv);
            } else if (g == 3) {
                __stcg(phs, hv);
            }
        }
        phs += H_;
        CLUSTER_ARRIVE();
        CLUSTER_WAIT();
    }

    // ---------------- projection: out = hs @ W_lin^T + b_lin ----------------
    {
        float* sWt   = sm;                  // [128 k][64 o]
        float* sTile = sm + 8192;           // [64 r][132]
        float* sBL   = sm + 8192 + 8448;
        for (int idx = tid; idx < H_ * O_; idx += THREADS) {
            int o = idx & 63, k = idx >> 6;
            sWt[k * 64 + o] = W_lin[o * H_ + k];
        }
        if (tid < O_) sBL[tid] = b_lin[tid];
        __syncthreads();

        const int t0 = hj * 256, row = tid >> 2, cg = tid & 3;  // 64 rows x 4 col-groups? 
        // 256 threads: row 0..63, cg 0..3 -> 16 cols each
        for (int it = 0; it < 16; it++) {
            int b = it >> 2, tr0 = t0 + (it & 3) * 64;
            const float* src = g_hs + ((size_t)(bg0 + b) * S_ + tr0) * H_;
            for (int idx = tid; idx < 64 * H_; idx += THREADS) {
                int r = idx >> 7, k = idx & 127;
                sTile[r * 132 + k] = src[idx];
            }
            __syncthreads();

            float accp[16];
#pragma unroll
            for (int j = 0; j < 16; j++) accp[j] = sBL[cg * 16 + j];
            const float* hrow = sTile + row * 132;
#pragma unroll 4
            for (int k4 = 0; k4 < 32; k4++) {
                float4 hx = *(const float4*)(hrow + k4 * 4);
#pragma unroll
                for (int kk = 0; kk < 4; kk++) {
                    float hv = (kk == 0) ? hx.x : (kk == 1) ? hx.y : (kk == 2) ? hx.z : hx.w;
                    const float* wr = sWt + (k4 * 4 + kk) * 64 + cg * 16;
#pragma unroll
                    for (int j = 0; j < 16; j++)
                        accp[j] = fmaf(hv, wr[j], accp[j]);
                }
            }
            float* orow = out + ((size_t)(bg0 + b) * S_ + tr0 + row) * O_ + cg * 16;
#pragma unroll
            for (int j = 0; j < 16; j += 4)
                *(float4*)(orow + j) = make_float4(accp[j], accp[j+1], accp[j+2], accp[j+3]);
            __syncthreads();
        }
    }
}

// ---------------- launch ----------------
extern "C" void kernel_launch(void* const* d_in, const int* in_sizes, int n_in,
                              void* d_out, int out_size)
{
    const float* x      = (const float*)d_in[0];
    const float* Wx_out = (const float*)d_in[1];
    const float* Wh_out = (const float*)d_in[2];
    const float* b_out  = (const float*)d_in[3];
    const float* Wx_in  = (const float*)d_in[4];
    const float* Wh_in  = (const float*)d_in[5];
    const float* b_in   = (const float*)d_in[6];
    const float* W_lin  = (const float*)d_in[7];
    const float* b_lin  = (const float*)d_in[8];
    float* out = (float*)d_out;

    prepass<<<dim3(8, GH, NC), 256>>>(x, Wx_out, b_out);

    (void)cudaFuncSetAttribute(nlstm_rec,
                               cudaFuncAttributeMaxDynamicSharedMemorySize, SMEM_BYTES);
    nlstm_rec<<<dim3(GH, NC), THREADS, SMEM_BYTES>>>(
        Wh_out, Wx_in, Wh_in, b_in, W_lin, b_lin, out);
}